// round 4
// baseline (speedup 1.0000x reference)
#include <cuda_runtime.h>

// Problem constants
#define BB    16384
#define FF    64
#define RR    1024
#define LL    4
#define PPAIR 128
#define CI    257      // 1 + F + F + P : [xatt 0..63][sq 64..127][inter 128..255][one 256]
#define TB    64       // batch tile per CTA
#define TR    64       // rule chunk
#define NCH   (RR / TR)   // 16
#define NT    256      // threads per CTA

// cdup row stride: 64 rules duplicated = 128 floats + 4 pad = 132 floats (528B, 16B aligned;
// consumer reads land on banks {0-3,8-11,16-19,24-27} -> conflict-free)
#define CSTRIDE 132

// Smem layout (floats)
#define OFF_PSM   0                        // [257][64]  = 16448
#define OFF_CDUP  16448                    // [257][132] = 33924
#define OFF_FIR   (16448 + 33924)          // [64][64]   = 4096
#define SMEM_FLOATS (OFF_FIR + 4096)       // 54468 floats = 217872 bytes

__device__ __forceinline__ void fma2(unsigned long long &d, unsigned long long a, unsigned long long b) {
    asm("fma.rn.f32x2 %0, %1, %2, %0;" : "+l"(d) : "l"(a), "l"(b));
}
__device__ __forceinline__ float2 up2(unsigned long long v) {
    float2 r;
    r.x = __uint_as_float((unsigned)(v & 0xFFFFFFFFull));
    r.y = __uint_as_float((unsigned)(v >> 32));
    return r;
}

extern "C" __global__ void __launch_bounds__(NT, 1)
anfis_fused_kernel(const float* __restrict__ x,
                   const float* __restrict__ aw,
                   const float* __restrict__ prm,
                   const float* __restrict__ thr,
                   const float* __restrict__ sgn,
                   const float* __restrict__ msk,
                   const float* __restrict__ Cq,
                   const int*   __restrict__ fidx,
                   const int*   __restrict__ ipair,
                   float* __restrict__ out)
{
    extern __shared__ float sm[];
    float* psm  = sm + OFF_PSM;    // p[i][b], i in [0,257), b in [0,64)
    float* cdup = sm + OFF_CDUP;   // cdup[i*CSTRIDE + 2*r + {0,1}] = C[chunk_r][i] duplicated
    float* fir  = sm + OFF_FIR;    // fir[r_local][b]

    const int t   = threadIdx.x;
    const int cta = blockIdx.x;

    // ---------------- Phase A: x_att into psm rows [0,64) (transposed) -------------
    {
        const float4* xg = reinterpret_cast<const float4*>(x + (size_t)cta * TB * FF);
        #pragma unroll
        for (int k = 0; k < 4; ++k) {
            int f4 = t + k * NT;          // 0..1023 float4 index in tile
            int bl = f4 >> 4;             // 16 float4 per row
            int fp = (f4 & 15) * 4;
            float4 v = xg[f4];
            psm[(fp + 0) * TB + bl] = v.x * aw[fp + 0];
            psm[(fp + 1) * TB + bl] = v.y * aw[fp + 1];
            psm[(fp + 2) * TB + bl] = v.z * aw[fp + 2];
            psm[(fp + 3) * TB + bl] = v.w * aw[fp + 3];
        }
    }
    __syncthreads();

    // ---------------- Phase B: squares, interactions, ones -------------------------
    #pragma unroll
    for (int k = 0; k < 16; ++k) {            // 4096 squares
        int e = t + k * NT;
        int f = e >> 6, b = e & 63;
        float v = psm[f * TB + b];
        psm[(64 + f) * TB + b] = v * v;
    }
    {
        const int2* ip2 = reinterpret_cast<const int2*>(ipair);
        #pragma unroll
        for (int k = 0; k < 32; ++k) {        // 8192 interaction entries
            int e = t + k * NT;
            int pi = e >> 6, b = e & 63;
            int2 pr = ip2[pi];
            psm[(128 + pi) * TB + b] = psm[pr.x * TB + b] * psm[pr.y * TB + b];
        }
    }
    if (t < TB) psm[256 * TB + t] = 1.0f;
    __syncthreads();

    // ---------------- Roles ---------------------------------------------------------
    // firing role: b = t&63, rule-group rg = t>>6 (each thread: 16 rules/chunk)
    const int fb = t & 63;
    const int rg = t >> 6;
    // GEMM role: per-thread 4b x 4r tile; bijection chosen so each WARP spans
    // 8 bq-values x 4 rq-values  ->  pv LDS.128 = 8 unique 16B segs = 1 phase.
    const int lane = t & 31;
    const int w    = t >> 5;
    const int bq = (lane & 7) | ((w & 1) << 3);         // [0,16)
    const int rq = ((lane >> 3) & 3) | ((w >> 1) << 2); // [0,16)

    float ssum = 0.0f;
    float yp0 = 0.f, yp1 = 0.f, yp2 = 0.f, yp3 = 0.f;

    const float4* th4 = reinterpret_cast<const float4*>(thr);
    const float4* sg4 = reinterpret_cast<const float4*>(sgn);
    const float4* mk4 = reinterpret_cast<const float4*>(msk);
    const int4*   fx4 = reinterpret_cast<const int4*>(fidx);

    float2* cdup2 = reinterpret_cast<float2*>(cdup);

    // Incremental (r,i) walk for the C producer: e starts at t, steps by NT.
    // r0/i0 computed once; per step i += NT, wrap while i >= CI.
    int pr0 = t / CI;
    int pi0 = t - pr0 * CI;

    for (int ch = 0; ch < NCH; ++ch) {
        // ---- Producer: load C chunk (coalesced scalar) duplicated into padded smem ----
        {
            const float* Cg = Cq + (size_t)ch * TR * CI;
            int r = pr0, i = pi0;
            for (int e = t; e < TR * CI; e += NT) {     // 16448 elements, 65 iters max
                float v = Cg[e];
                cdup2[i * (CSTRIDE / 2) + r] = make_float2(v, v);
                i += NT;
                if (i >= CI) { i -= CI; ++r; }          // NT < 2*CI, single wrap possible
            }
        }
        // ---- Producer: firing for this rule chunk ----
        // prod_l masked_sigmoid = 1 / prod_l (1 + mask_l * exp(-z_l))
        #pragma unroll 4
        for (int k = 0; k < 16; ++k) {
            int rl = rg * 16 + k;
            int r  = ch * TR + rl;
            int4   fi = fx4[r];
            float4 th = th4[r];
            float4 sg = sg4[r];
            float4 mk = mk4[r];
            float  pp = prm[r];
            float a0 = -pp * sg.x, a1 = -pp * sg.y, a2 = -pp * sg.z, a3 = -pp * sg.w;
            float e0 = __expf(a0 * (psm[fi.x * TB + fb] - th.x));
            float e1 = __expf(a1 * (psm[fi.y * TB + fb] - th.y));
            float e2 = __expf(a2 * (psm[fi.z * TB + fb] - th.z));
            float e3 = __expf(a3 * (psm[fi.w * TB + fb] - th.w));
            float t0 = fmaf(mk.x, e0, 1.0f);
            float t1 = fmaf(mk.y, e1, 1.0f);
            float t2 = fmaf(mk.z, e2, 1.0f);
            float t3 = fmaf(mk.w, e3, 1.0f);
            float f  = __fdividef(1.0f, (t0 * t1) * (t2 * t3));
            fir[rl * TB + fb] = f;
            ssum += f;
        }
        __syncthreads();   // cdup + fir ready

        // ---- Consumer: D[b][r] = sum_i p[b,i] * C[r,i], packed f32x2 over b-pairs ----
        unsigned long long a00 = 0, a01 = 0, a10 = 0, a11 = 0,
                           a20 = 0, a21 = 0, a30 = 0, a31 = 0;
        const float* pbase = psm  + bq * 4;
        const float* cbase = cdup + rq * 8;
        #pragma unroll 4
        for (int i = 0; i < CI; ++i) {
            ulonglong2 pv  = *reinterpret_cast<const ulonglong2*>(pbase + i * TB);           // (b0,b1),(b2,b3)
            ulonglong2 c01 = *reinterpret_cast<const ulonglong2*>(cbase + i * CSTRIDE);      // (c0,c0),(c1,c1)
            ulonglong2 c23 = *reinterpret_cast<const ulonglong2*>(cbase + i * CSTRIDE + 4);  // (c2,c2),(c3,c3)
            fma2(a00, pv.x, c01.x);  fma2(a01, pv.y, c01.x);
            fma2(a10, pv.x, c01.y);  fma2(a11, pv.y, c01.y);
            fma2(a20, pv.x, c23.x);  fma2(a21, pv.y, c23.x);
            fma2(a30, pv.x, c23.y);  fma2(a31, pv.y, c23.y);
        }
        // ---- Epilogue: yp[b] += fir[r][b] * D[b][r] ----
        {
            const float* fbp = fir + bq * 4;
            {
                float4 fv = *reinterpret_cast<const float4*>(fbp + (rq * 4 + 0) * TB);
                float2 lo = up2(a00), hi = up2(a01);
                yp0 = fmaf(fv.x, lo.x, yp0); yp1 = fmaf(fv.y, lo.y, yp1);
                yp2 = fmaf(fv.z, hi.x, yp2); yp3 = fmaf(fv.w, hi.y, yp3);
            }
            {
                float4 fv = *reinterpret_cast<const float4*>(fbp + (rq * 4 + 1) * TB);
                float2 lo = up2(a10), hi = up2(a11);
                yp0 = fmaf(fv.x, lo.x, yp0); yp1 = fmaf(fv.y, lo.y, yp1);
                yp2 = fmaf(fv.z, hi.x, yp2); yp3 = fmaf(fv.w, hi.y, yp3);
            }
            {
                float4 fv = *reinterpret_cast<const float4*>(fbp + (rq * 4 + 2) * TB);
                float2 lo = up2(a20), hi = up2(a21);
                yp0 = fmaf(fv.x, lo.x, yp0); yp1 = fmaf(fv.y, lo.y, yp1);
                yp2 = fmaf(fv.z, hi.x, yp2); yp3 = fmaf(fv.w, hi.y, yp3);
            }
            {
                float4 fv = *reinterpret_cast<const float4*>(fbp + (rq * 4 + 3) * TB);
                float2 lo = up2(a30), hi = up2(a31);
                yp0 = fmaf(fv.x, lo.x, yp0); yp1 = fmaf(fv.y, lo.y, yp1);
                yp2 = fmaf(fv.z, hi.x, yp2); yp3 = fmaf(fv.w, hi.y, yp3);
            }
        }
        __syncthreads();   // before next chunk overwrites cdup/fir
    }

    // ---------------- Deterministic reductions (no float atomics) -------------------
    // reuse fir buffer: [0,1024) y-partials by (rq,b), [1024,1280) ssum partials by rg
    float* red  = fir;
    float* sred = fir + 1024;
    *reinterpret_cast<float4*>(&red[rq * 64 + bq * 4]) = make_float4(yp0, yp1, yp2, yp3);
    sred[rg * 64 + fb] = ssum;
    __syncthreads();

    if (t < TB) {
        float ys = 0.0f;
        #pragma unroll
        for (int q = 0; q < 16; ++q) ys += red[q * 64 + t];
        float ss = ((sred[t] + sred[64 + t]) + (sred[128 + t] + sred[192 + t]));
        out[cta * TB + t] = ys / (ss + 1e-8f);
    }
}

extern "C" void kernel_launch(void* const* d_in, const int* in_sizes, int n_in,
                              void* d_out, int out_size) {
    const float* x    = (const float*)d_in[0];
    const float* aw   = (const float*)d_in[1];
    const float* prm  = (const float*)d_in[2];
    const float* thr  = (const float*)d_in[3];
    const float* sgn  = (const float*)d_in[4];
    const float* msk  = (const float*)d_in[5];
    const float* Cq   = (const float*)d_in[6];
    const int*   fidx = (const int*)d_in[7];
    const int*   ip   = (const int*)d_in[8];
    float* out = (float*)d_out;

    const size_t smem_bytes = (size_t)SMEM_FLOATS * sizeof(float);
    cudaFuncSetAttribute(anfis_fused_kernel,
                         cudaFuncAttributeMaxDynamicSharedMemorySize,
                         (int)smem_bytes);

    anfis_fused_kernel<<<BB / TB, NT, smem_bytes>>>(x, aw, prm, thr, sgn, msk, Cq, fidx, ip, out);
}

// round 7
// speedup vs baseline: 1.1732x; 1.1732x over previous
#include <cuda_runtime.h>

// Problem constants
#define BB    16384
#define FF    64
#define RR    1024
#define CI    257      // 1 + F + F + P : [xatt 0..63][sq 64..127][inter 128..255][one 256]
#define TB    64       // batch tile per CTA
#define TR    64       // rule chunk
#define NCH   (RR / TR)   // 16
#define NT    512      // threads per CTA  (16 warps)

#define ISPLIT 129     // sk0: i in [0,129), sk1: [129,257)

// cdup row stride: 64 rules duplicated = 128 floats + 4 pad = 132 floats
#define CSTRIDE 132

// Smem layout (floats)
#define OFF_PSM   0                        // [257][64]  = 16448
#define OFF_CDUP  16448                    // [257][132] = 33924
#define OFF_FIR   (16448 + 33924)          // [64][64]   = 4096 (also reduction scratch)
#define SMEM_FLOATS (OFF_FIR + 4096)       // 54468 floats = 217872 bytes

__device__ __forceinline__ void fma2(unsigned long long &d, unsigned long long a, unsigned long long b) {
    asm("fma.rn.f32x2 %0, %1, %2, %0;" : "+l"(d) : "l"(a), "l"(b));
}
__device__ __forceinline__ float2 up2(unsigned long long v) {
    float2 r;
    r.x = __uint_as_float((unsigned)(v & 0xFFFFFFFFull));
    r.y = __uint_as_float((unsigned)(v >> 32));
    return r;
}

extern "C" __global__ void __launch_bounds__(NT, 1)
anfis_fused_kernel(const float* __restrict__ x,
                   const float* __restrict__ aw,
                   const float* __restrict__ prm,
                   const float* __restrict__ thr,
                   const float* __restrict__ sgn,
                   const float* __restrict__ msk,
                   const float* __restrict__ Cq,
                   const int*   __restrict__ fidx,
                   const int*   __restrict__ ipair,
                   float* __restrict__ out)
{
    extern __shared__ float sm[];
    float* psm  = sm + OFF_PSM;    // p[i][b]
    float* cdup = sm + OFF_CDUP;   // cdup[i*CSTRIDE + 2r] = C[r][i] duplicated
    float* fir  = sm + OFF_FIR;    // fir[r_local][b]

    const int t   = threadIdx.x;
    const int cta = blockIdx.x;

    // ---------------- Phase A: x_att into psm (transposed) -------------------------
    {
        const float4* xg = reinterpret_cast<const float4*>(x + (size_t)cta * TB * FF);
        #pragma unroll
        for (int k = 0; k < 2; ++k) {
            int f4 = t + k * NT;          // 0..1023
            int bl = f4 >> 4;
            int fp = (f4 & 15) * 4;
            float4 v = xg[f4];
            psm[(fp + 0) * TB + bl] = v.x * aw[fp + 0];
            psm[(fp + 1) * TB + bl] = v.y * aw[fp + 1];
            psm[(fp + 2) * TB + bl] = v.z * aw[fp + 2];
            psm[(fp + 3) * TB + bl] = v.w * aw[fp + 3];
        }
    }
    __syncthreads();

    // ---------------- Phase B: squares, interactions, ones -------------------------
    #pragma unroll
    for (int k = 0; k < 8; ++k) {             // 4096 squares
        int e = t + k * NT;
        int f = e >> 6, b = e & 63;
        float v = psm[f * TB + b];
        psm[(64 + f) * TB + b] = v * v;
    }
    {
        const int2* ip2 = reinterpret_cast<const int2*>(ipair);
        #pragma unroll
        for (int k = 0; k < 16; ++k) {        // 8192 interaction entries
            int e = t + k * NT;
            int pi = e >> 6, b = e & 63;
            int2 pr = ip2[pi];
            psm[(128 + pi) * TB + b] = psm[pr.x * TB + b] * psm[pr.y * TB + b];
        }
    }
    if (t < TB) psm[256 * TB + t] = 1.0f;
    __syncthreads();

    // ---------------- Roles ---------------------------------------------------------
    // firing role: each thread handles 8 rules/chunk
    const int fb = t & 63;
    const int rg = t >> 6;                    // [0,8)
    // GEMM role: split-K over i. Two 256-thread groups, each 16bq x 16rq of 4b x 4r.
    const int lane = t & 31;
    const int w    = t >> 5;                  // [0,16)
    const int sk   = w >> 3;                  // 0 or 1
    const int wl   = w & 7;
    const int bq = (lane & 7) | ((wl & 1) << 3);         // [0,16)
    const int rq = ((lane >> 3) & 3) | ((wl >> 1) << 2); // [0,16)
    const int i0 = sk ? ISPLIT : 0;
    const int i1 = sk ? CI : ISPLIT;

    float ssum = 0.0f;
    float yp0 = 0.f, yp1 = 0.f, yp2 = 0.f, yp3 = 0.f;

    const float4* th4 = reinterpret_cast<const float4*>(thr);
    const float4* sg4 = reinterpret_cast<const float4*>(sgn);
    const float4* mk4 = reinterpret_cast<const float4*>(msk);
    const int4*   fx4 = reinterpret_cast<const int4*>(fidx);

    float2* cdup2 = reinterpret_cast<float2*>(cdup);

    // incremental (r,i) walk for the C producer (stride NT=512 over e = r*CI + i)
    const int pr0 = t / CI;
    const int pi0 = t - pr0 * CI;

    const float* pbase = psm  + bq * 4;
    const float* cbase = cdup + rq * 8;

    for (int ch = 0; ch < NCH; ++ch) {
        // ---- Producer: C chunk -> duplicated padded smem (coalesced LDG) ----
        {
            const float* Cg = Cq + (size_t)ch * TR * CI;
            int r = pr0, i = pi0;
            for (int e = t; e < TR * CI; e += NT) {     // 33 iters
                float v = Cg[e];
                cdup2[i * (CSTRIDE / 2) + r] = make_float2(v, v);
                i += NT - CI; ++r;                      // e += 512: i += 255, r += 1
                if (i >= CI) { i -= CI; ++r; }          // possible second wrap
            }
        }
        // ---- Producer: firing for this rule chunk ----
        #pragma unroll
        for (int k = 0; k < 8; ++k) {
            int rl = rg * 8 + k;
            int r  = ch * TR + rl;
            int4   fi = fx4[r];
            float4 th = th4[r];
            float4 sg = sg4[r];
            float4 mk = mk4[r];
            float  pp = prm[r];
            float a0 = -pp * sg.x, a1 = -pp * sg.y, a2 = -pp * sg.z, a3 = -pp * sg.w;
            float e0 = __expf(a0 * (psm[fi.x * TB + fb] - th.x));
            float e1 = __expf(a1 * (psm[fi.y * TB + fb] - th.y));
            float e2 = __expf(a2 * (psm[fi.z * TB + fb] - th.z));
            float e3 = __expf(a3 * (psm[fi.w * TB + fb] - th.w));
            float t0 = fmaf(mk.x, e0, 1.0f);
            float t1 = fmaf(mk.y, e1, 1.0f);
            float t2 = fmaf(mk.z, e2, 1.0f);
            float t3 = fmaf(mk.w, e3, 1.0f);
            float f  = __fdividef(1.0f, (t0 * t1) * (t2 * t3));
            fir[rl * TB + fb] = f;
            ssum += f;
        }
        __syncthreads();   // cdup + fir ready

        // ---- Consumer: partial D over this group's i-range, 1-deep prefetch ----
        unsigned long long a00 = 0, a01 = 0, a10 = 0, a11 = 0,
                           a20 = 0, a21 = 0, a30 = 0, a31 = 0;
        {
            ulonglong2 pv  = *reinterpret_cast<const ulonglong2*>(pbase + i0 * TB);
            ulonglong2 c01 = *reinterpret_cast<const ulonglong2*>(cbase + i0 * CSTRIDE);
            ulonglong2 c23 = *reinterpret_cast<const ulonglong2*>(cbase + i0 * CSTRIDE + 4);
            #pragma unroll 4
            for (int i = i0; i < i1 - 1; ++i) {
                ulonglong2 pvn  = *reinterpret_cast<const ulonglong2*>(pbase + (i + 1) * TB);
                ulonglong2 c01n = *reinterpret_cast<const ulonglong2*>(cbase + (i + 1) * CSTRIDE);
                ulonglong2 c23n = *reinterpret_cast<const ulonglong2*>(cbase + (i + 1) * CSTRIDE + 4);
                fma2(a00, pv.x, c01.x);  fma2(a01, pv.y, c01.x);
                fma2(a10, pv.x, c01.y);  fma2(a11, pv.y, c01.y);
                fma2(a20, pv.x, c23.x);  fma2(a21, pv.y, c23.x);
                fma2(a30, pv.x, c23.y);  fma2(a31, pv.y, c23.y);
                pv = pvn; c01 = c01n; c23 = c23n;
            }
            fma2(a00, pv.x, c01.x);  fma2(a01, pv.y, c01.x);
            fma2(a10, pv.x, c01.y);  fma2(a11, pv.y, c01.y);
            fma2(a20, pv.x, c23.x);  fma2(a21, pv.y, c23.x);
            fma2(a30, pv.x, c23.y);  fma2(a31, pv.y, c23.y);
        }
        // ---- Epilogue: yp[b] += fir[r][b] * Dpartial[b][r] (both sk groups) ----
        {
            const float* fbp = fir + bq * 4;
            {
                float4 fv = *reinterpret_cast<const float4*>(fbp + (rq * 4 + 0) * TB);
                float2 lo = up2(a00), hi = up2(a01);
                yp0 = fmaf(fv.x, lo.x, yp0); yp1 = fmaf(fv.y, lo.y, yp1);
                yp2 = fmaf(fv.z, hi.x, yp2); yp3 = fmaf(fv.w, hi.y, yp3);
            }
            {
                float4 fv = *reinterpret_cast<const float4*>(fbp + (rq * 4 + 1) * TB);
                float2 lo = up2(a10), hi = up2(a11);
                yp0 = fmaf(fv.x, lo.x, yp0); yp1 = fmaf(fv.y, lo.y, yp1);
                yp2 = fmaf(fv.z, hi.x, yp2); yp3 = fmaf(fv.w, hi.y, yp3);
            }
            {
                float4 fv = *reinterpret_cast<const float4*>(fbp + (rq * 4 + 2) * TB);
                float2 lo = up2(a20), hi = up2(a21);
                yp0 = fmaf(fv.x, lo.x, yp0); yp1 = fmaf(fv.y, lo.y, yp1);
                yp2 = fmaf(fv.z, hi.x, yp2); yp3 = fmaf(fv.w, hi.y, yp3);
            }
            {
                float4 fv = *reinterpret_cast<const float4*>(fbp + (rq * 4 + 3) * TB);
                float2 lo = up2(a30), hi = up2(a31);
                yp0 = fmaf(fv.x, lo.x, yp0); yp1 = fmaf(fv.y, lo.y, yp1);
                yp2 = fmaf(fv.z, hi.x, yp2); yp3 = fmaf(fv.w, hi.y, yp3);
            }
        }
        __syncthreads();   // before next chunk overwrites cdup/fir
    }

    // ---------------- Deterministic reductions (no float atomics) -------------------
    // reuse fir region: [0,2048) y-partials by (sk,rq,b), [2048,2560) ssum by rg
    float* red  = fir;
    float* sred = fir + 2048;
    *reinterpret_cast<float4*>(&red[sk * 1024 + rq * 64 + bq * 4]) = make_float4(yp0, yp1, yp2, yp3);
    sred[rg * 64 + fb] = ssum;
    __syncthreads();

    if (t < TB) {
        float ys = 0.0f;
        #pragma unroll
        for (int q = 0; q < 32; ++q) ys += red[q * 64 + t];
        float ss = 0.0f;
        #pragma unroll
        for (int g = 0; g < 8; ++g) ss += sred[g * 64 + t];
        out[cta * TB + t] = ys / (ss + 1e-8f);
    }
}

extern "C" void kernel_launch(void* const* d_in, const int* in_sizes, int n_in,
                              void* d_out, int out_size) {
    const float* x    = (const float*)d_in[0];
    const float* aw   = (const float*)d_in[1];
    const float* prm  = (const float*)d_in[2];
    const float* thr  = (const float*)d_in[3];
    const float* sgn  = (const float*)d_in[4];
    const float* msk  = (const float*)d_in[5];
    const float* Cq   = (const float*)d_in[6];
    const int*   fidx = (const int*)d_in[7];
    const int*   ip   = (const int*)d_in[8];
    float* out = (float*)d_out;

    const size_t smem_bytes = (size_t)SMEM_FLOATS * sizeof(float);
    cudaFuncSetAttribute(anfis_fused_kernel,
                         cudaFuncAttributeMaxDynamicSharedMemorySize,
                         (int)smem_bytes);

    anfis_fused_kernel<<<BB / TB, NT, smem_bytes>>>(x, aw, prm, thr, sgn, msk, Cq, fidx, ip, out);
}